// round 2
// baseline (speedup 1.0000x reference)
#include <cuda_runtime.h>

#define TT   1000
#define NCH  4096

// scratch (no cudaMalloc allowed)
__device__ float g_seq[NCH * TT];     // LSTM input, [chain][t], 16 MB
__device__ float g_feat[NCH * 32];    // [chain][ h_fwd(16) | h_bwd(16) ]

typedef unsigned long long u64;

// ---- packed f32x2 helpers (Blackwell FFMA2 path) ----
__device__ __forceinline__ u64 pack2(float lo, float hi) {
    u64 r; asm("mov.b64 %0, {%1, %2};" : "=l"(r) : "f"(lo), "f"(hi)); return r;
}
__device__ __forceinline__ void unpack2(u64 v, float& lo, float& hi) {
    asm("mov.b64 {%0, %1}, %2;" : "=f"(lo), "=f"(hi) : "l"(v));
}
__device__ __forceinline__ u64 fma2(u64 a, u64 b, u64 c) {
    u64 d; asm("fma.rn.f32x2 %0, %1, %2, %3;" : "=l"(d) : "l"(a), "l"(b), "l"(c)); return d;
}
__device__ __forceinline__ u64 mul2(u64 a, u64 b) {
    u64 d; asm("mul.rn.f32x2 %0, %1, %2;" : "=l"(d) : "l"(a), "l"(b)); return d;
}
__device__ __forceinline__ u64 shfl64_16(u64 v, int src) {
    return (u64)__shfl_sync(0xffffffffu, (long long)v, src, 16);
}

__device__ __forceinline__ float gelu_exact(float v) {
    return 0.5f * v * (1.0f + erff(v * 0.70710678118654752f));
}
__device__ __forceinline__ float fast_sig(float x) {
    return __fdividef(1.0f, 1.0f + __expf(-x));
}
__device__ __forceinline__ float fast_tanh(float x) {
    float e = __expf(-2.0f * fabsf(x));
    float r = __fdividef(1.0f - e, 1.0f + e);
    return copysignf(r, x);
}
__device__ __forceinline__ u64 sig2(u64 x) {
    float a, b; unpack2(x, a, b);
    return pack2(fast_sig(a), fast_sig(b));
}
__device__ __forceinline__ u64 tanh2(u64 x) {
    float a, b; unpack2(x, a, b);
    return pack2(fast_tanh(a), fast_tanh(b));
}

// ---------------------------------------------------------------------------
// Kernel 1: fused depthwise-conv(5,pad2)+BN+GELU  x2.  One block per (b,c) row.
// ---------------------------------------------------------------------------
__global__ void __launch_bounds__(256) prep_kernel(
    const float* __restrict__ x,
    const float* __restrict__ c1w, const float* __restrict__ c1b,
    const float* __restrict__ b1g, const float* __restrict__ b1b,
    const float* __restrict__ b1m, const float* __restrict__ b1v,
    const float* __restrict__ c2w, const float* __restrict__ c2b,
    const float* __restrict__ b2g, const float* __restrict__ b2b,
    const float* __restrict__ b2m, const float* __restrict__ b2v)
{
    __shared__ float xs[TT + 4];
    __shared__ float ys[TT + 4];

    const int chain = blockIdx.x;          // b*64 + c
    const int ch    = chain & 63;
    const int tid   = threadIdx.x;

    if (tid < 2) {
        xs[tid] = 0.0f; xs[TT + 2 + tid] = 0.0f;
        ys[tid] = 0.0f; ys[TT + 2 + tid] = 0.0f;
    }
    const float* xr = x + (size_t)chain * TT;
    for (int t = tid; t < TT; t += 256) xs[t + 2] = xr[t];

    const float w0 = c1w[ch * 5 + 0], w1 = c1w[ch * 5 + 1], w2 = c1w[ch * 5 + 2],
                w3 = c1w[ch * 5 + 3], w4 = c1w[ch * 5 + 4];
    const float s1 = b1g[ch] * rsqrtf(b1v[ch] + 1e-5f);
    const float d1 = (c1b[ch] - b1m[ch]) * s1 + b1b[ch];

    __syncthreads();
    for (int t = tid; t < TT; t += 256) {
        float a = xs[t] * w0;
        a = fmaf(xs[t + 1], w1, a);
        a = fmaf(xs[t + 2], w2, a);
        a = fmaf(xs[t + 3], w3, a);
        a = fmaf(xs[t + 4], w4, a);
        ys[t + 2] = gelu_exact(fmaf(a, s1, d1));
    }

    const float u0 = c2w[ch * 5 + 0], u1 = c2w[ch * 5 + 1], u2 = c2w[ch * 5 + 2],
                u3 = c2w[ch * 5 + 3], u4 = c2w[ch * 5 + 4];
    const float s2 = b2g[ch] * rsqrtf(b2v[ch] + 1e-5f);
    const float d2 = (c2b[ch] - b2m[ch]) * s2 + b2b[ch];

    __syncthreads();
    float* outr = g_seq + (size_t)chain * TT;
    for (int t = tid; t < TT; t += 256) {
        float a = ys[t] * u0;
        a = fmaf(ys[t + 1], u1, a);
        a = fmaf(ys[t + 2], u2, a);
        a = fmaf(ys[t + 3], u3, a);
        a = fmaf(ys[t + 4], u4, a);
        outr[t] = gelu_exact(fmaf(a, s2, d2));
    }
}

// ---------------------------------------------------------------------------
// Kernel 2: LSTM, both directions packed in f32x2 (fwd=lo, bwd=hi).
// 16 lanes per chain (one per hidden unit), h broadcast via 64-bit shfl.
// ---------------------------------------------------------------------------
__global__ void __launch_bounds__(128) lstm_kernel(
    const float* __restrict__ wihf, const float* __restrict__ whhf,
    const float* __restrict__ bihf, const float* __restrict__ bhhf,
    const float* __restrict__ wihr, const float* __restrict__ whhr,
    const float* __restrict__ bihr, const float* __restrict__ bhhr)
{
    const int tid   = threadIdx.x;
    const int j     = tid & 15;                     // hidden unit
    const int chain = blockIdx.x * 8 + (tid >> 4);  // 0..4095

    u64 W[4][16];   // packed (W_hh_fwd, W_hh_bwd) rows for gates i,f,g,o
    u64 wi[4], bb[4];
#pragma unroll
    for (int k = 0; k < 4; k++) {
        const int row = k * 16 + j;
        wi[k] = pack2(wihf[row], wihr[row]);
        bb[k] = pack2(bihf[row] + bhhf[row], bihr[row] + bhhr[row]);
#pragma unroll
        for (int i = 0; i < 16; i++)
            W[k][i] = pack2(whhf[row * 16 + i], whhr[row * 16 + i]);
    }

    const float* seq = g_seq + (size_t)chain * TT;
    u64 h = 0ull, c = 0ull;   // packed (fwd, bwd) state, starts at 0.0f|0.0f

    for (int t0 = 0; t0 < TT; t0 += 16) {
        const int steps = (TT - t0) < 16 ? (TT - t0) : 16;
        const int tl    = t0 + j;
        u64 xv = 0ull;
        if (tl < TT) xv = pack2(seq[tl], seq[TT - 1 - tl]);  // two coalesced 64B runs

        for (int i = 0; i < steps; i++) {
            const u64 xt = shfl64_16(xv, i);
            u64 g0 = fma2(xt, wi[0], bb[0]);
            u64 g1 = fma2(xt, wi[1], bb[1]);
            u64 g2 = fma2(xt, wi[2], bb[2]);
            u64 g3 = fma2(xt, wi[3], bb[3]);
#pragma unroll
            for (int ii = 0; ii < 16; ii++) {
                const u64 hv = shfl64_16(h, ii);   // (h_f[ii], h_b[ii])
                g0 = fma2(hv, W[0][ii], g0);
                g1 = fma2(hv, W[1][ii], g1);
                g2 = fma2(hv, W[2][ii], g2);
                g3 = fma2(hv, W[3][ii], g3);
            }
            const u64 ig = sig2(g0);
            const u64 fg = sig2(g1);
            const u64 gg = tanh2(g2);
            const u64 og = sig2(g3);
            c = fma2(fg, c, mul2(ig, gg));
            h = mul2(og, tanh2(c));
        }
    }

    float hf, hb; unpack2(h, hf, hb);
    g_feat[chain * 32 + j]      = hf;
    g_feat[chain * 32 + 16 + j] = hb;
}

// ---------------------------------------------------------------------------
// Kernel 3: out[n,e] = feat[n,:] . lin_w[e,:] + lin_b[e]
// ---------------------------------------------------------------------------
__global__ void __launch_bounds__(256) linear_kernel(
    const float* __restrict__ lw, const float* __restrict__ lb,
    float* __restrict__ out)
{
    const int idx = blockIdx.x * 256 + threadIdx.x;    // 131072 total
    const int n = idx >> 5;
    const int e = idx & 31;
    const float* f = g_feat + n * 32;
    const float* w = lw + e * 32;
    float acc = lb[e];
#pragma unroll
    for (int k = 0; k < 32; k++) acc = fmaf(f[k], w[k], acc);
    out[idx] = acc;
}

// ---------------------------------------------------------------------------
extern "C" void kernel_launch(void* const* d_in, const int* in_sizes, int n_in,
                              void* d_out, int out_size)
{
    const float* x      = (const float*)d_in[0];
    const float* c1w    = (const float*)d_in[1];
    const float* c1b    = (const float*)d_in[2];
    const float* b1g    = (const float*)d_in[3];
    const float* b1b    = (const float*)d_in[4];
    const float* b1m    = (const float*)d_in[5];
    const float* b1v    = (const float*)d_in[6];
    const float* c2w    = (const float*)d_in[7];
    const float* c2b    = (const float*)d_in[8];
    const float* b2g    = (const float*)d_in[9];
    const float* b2b    = (const float*)d_in[10];
    const float* b2m    = (const float*)d_in[11];
    const float* b2v    = (const float*)d_in[12];
    const float* wihf   = (const float*)d_in[13];
    const float* whhf   = (const float*)d_in[14];
    const float* bihf   = (const float*)d_in[15];
    const float* bhhf   = (const float*)d_in[16];
    const float* wihr   = (const float*)d_in[17];
    const float* whhr   = (const float*)d_in[18];
    const float* bihr   = (const float*)d_in[19];
    const float* bhhr   = (const float*)d_in[20];
    const float* lw     = (const float*)d_in[21];
    const float* lb     = (const float*)d_in[22];
    float* out = (float*)d_out;

    prep_kernel<<<NCH, 256>>>(x, c1w, c1b, b1g, b1b, b1m, b1v,
                              c2w, c2b, b2g, b2b, b2m, b2v);
    lstm_kernel<<<NCH / 8, 128>>>(wihf, whhf, bihf, bhhf,
                                  wihr, whhr, bihr, bhhr);
    linear_kernel<<<(NCH * 32) / 256, 256>>>(lw, lb, out);
}

// round 3
// speedup vs baseline: 1.3432x; 1.3432x over previous
#include <cuda_runtime.h>

#define TT   1000
#define NCH  4096

// scratch (no cudaMalloc allowed)
__device__ float g_seq[NCH * TT];     // LSTM input, [chain][t], 16 MB
__device__ float g_feat[NCH * 32];    // [chain][ h_fwd(16) | h_bwd(16) ]

typedef unsigned long long u64;

// ---- packed f32x2 helpers (Blackwell FFMA2 path) ----
__device__ __forceinline__ u64 pack2(float lo, float hi) {
    u64 r; asm("mov.b64 %0, {%1, %2};" : "=l"(r) : "f"(lo), "f"(hi)); return r;
}
__device__ __forceinline__ void unpack2(u64 v, float& lo, float& hi) {
    asm("mov.b64 {%0, %1}, %2;" : "=f"(lo), "=f"(hi) : "l"(v));
}
__device__ __forceinline__ u64 fma2(u64 a, u64 b, u64 c) {
    u64 d; asm("fma.rn.f32x2 %0, %1, %2, %3;" : "=l"(d) : "l"(a), "l"(b), "l"(c)); return d;
}
__device__ __forceinline__ u64 mul2(u64 a, u64 b) {
    u64 d; asm("mul.rn.f32x2 %0, %1, %2;" : "=l"(d) : "l"(a), "l"(b)); return d;
}
__device__ __forceinline__ u64 shfl64_16(u64 v, int src) {
    return (u64)__shfl_sync(0xffffffffu, (long long)v, src, 16);
}
__device__ __forceinline__ float ex2f(float x) {
    float r; asm("ex2.approx.f32 %0, %1;" : "=f"(r) : "f"(x)); return r;
}
__device__ __forceinline__ float rcpf(float x) {
    float r; asm("rcp.approx.f32 %0, %1;" : "=f"(r) : "f"(x)); return r;
}

__device__ __forceinline__ float gelu_exact(float v) {
    return 0.5f * v * (1.0f + erff(v * 0.70710678118654752f));
}

// ---------------------------------------------------------------------------
// Kernel 1: fused depthwise-conv(5,pad2)+BN+GELU  x2.  One block per (b,c) row.
// ---------------------------------------------------------------------------
__global__ void __launch_bounds__(256) prep_kernel(
    const float* __restrict__ x,
    const float* __restrict__ c1w, const float* __restrict__ c1b,
    const float* __restrict__ b1g, const float* __restrict__ b1b,
    const float* __restrict__ b1m, const float* __restrict__ b1v,
    const float* __restrict__ c2w, const float* __restrict__ c2b,
    const float* __restrict__ b2g, const float* __restrict__ b2b,
    const float* __restrict__ b2m, const float* __restrict__ b2v)
{
    __shared__ float xs[TT + 4];
    __shared__ float ys[TT + 4];

    const int chain = blockIdx.x;          // b*64 + c
    const int ch    = chain & 63;
    const int tid   = threadIdx.x;

    if (tid < 2) {
        xs[tid] = 0.0f; xs[TT + 2 + tid] = 0.0f;
        ys[tid] = 0.0f; ys[TT + 2 + tid] = 0.0f;
    }
    const float* xr = x + (size_t)chain * TT;
    for (int t = tid; t < TT; t += 256) xs[t + 2] = xr[t];

    const float w0 = c1w[ch * 5 + 0], w1 = c1w[ch * 5 + 1], w2 = c1w[ch * 5 + 2],
                w3 = c1w[ch * 5 + 3], w4 = c1w[ch * 5 + 4];
    const float s1 = b1g[ch] * rsqrtf(b1v[ch] + 1e-5f);
    const float d1 = (c1b[ch] - b1m[ch]) * s1 + b1b[ch];

    __syncthreads();
    for (int t = tid; t < TT; t += 256) {
        float a = xs[t] * w0;
        a = fmaf(xs[t + 1], w1, a);
        a = fmaf(xs[t + 2], w2, a);
        a = fmaf(xs[t + 3], w3, a);
        a = fmaf(xs[t + 4], w4, a);
        ys[t + 2] = gelu_exact(fmaf(a, s1, d1));
    }

    const float u0 = c2w[ch * 5 + 0], u1 = c2w[ch * 5 + 1], u2 = c2w[ch * 5 + 2],
                u3 = c2w[ch * 5 + 3], u4 = c2w[ch * 5 + 4];
    const float s2 = b2g[ch] * rsqrtf(b2v[ch] + 1e-5f);
    const float d2 = (c2b[ch] - b2m[ch]) * s2 + b2b[ch];

    __syncthreads();
    float* outr = g_seq + (size_t)chain * TT;
    for (int t = tid; t < TT; t += 256) {
        float a = ys[t] * u0;
        a = fmaf(ys[t + 1], u1, a);
        a = fmaf(ys[t + 2], u2, a);
        a = fmaf(ys[t + 3], u3, a);
        a = fmaf(ys[t + 4], u4, a);
        outr[t] = gelu_exact(fmaf(a, s2, d2));
    }
}

// ---------------------------------------------------------------------------
// Kernel 2: LSTM, TWO SAME-DIRECTION CHAINS packed per f32x2 lane.
// 16 lanes per chain-pair (one hidden unit each), h broadcast via 64-bit shfl.
// Weights are splatted (w,w) at init -> FFMA2 operands need no per-step movs.
// Packed units: pu in [0,2048) = fwd pairs, [2048,4096) = bwd pairs.
// ---------------------------------------------------------------------------
__global__ void __launch_bounds__(128) lstm_kernel(
    const float* __restrict__ wihf, const float* __restrict__ whhf,
    const float* __restrict__ bihf, const float* __restrict__ bhhf,
    const float* __restrict__ wihr, const float* __restrict__ whhr,
    const float* __restrict__ bihr, const float* __restrict__ bhhr)
{
    const int tid = threadIdx.x;
    const int j   = tid & 15;                      // hidden unit
    const int pu  = blockIdx.x * 8 + (tid >> 4);   // 0..4095 packed units
    const bool bwd = (pu >= 2048);
    const int pairIdx = bwd ? pu - 2048 : pu;
    const int chainA  = 2 * pairIdx;
    const int chainB  = 2 * pairIdx + 1;

    const float* wih = bwd ? wihr : wihf;
    const float* whh = bwd ? whhr : whhf;
    const float* bih = bwd ? bihr : bihf;
    const float* bhh = bwd ? bhhr : bhhf;

    // splatted weights: identical for both packed chains
    u64 W[4][16];
    u64 wi[4], bb[4];
#pragma unroll
    for (int k = 0; k < 4; k++) {
        const int row = k * 16 + j;
        const float wv = wih[row];
        const float bv = bih[row] + bhh[row];
        wi[k] = pack2(wv, wv);
        bb[k] = pack2(bv, bv);
#pragma unroll
        for (int i = 0; i < 16; i++) {
            const float w = whh[row * 16 + i];
            W[k][i] = pack2(w, w);
        }
    }

    // hoisted packed constants
    const u64 ONE2   = pack2(1.0f, 1.0f);
    const u64 NONE2  = pack2(-1.0f, -1.0f);
    const u64 NL2E   = pack2(-1.4426950408889634f, -1.4426950408889634f);
    const u64 N2L2E  = pack2(-2.8853900817779268f, -2.8853900817779268f);
    const u64 ABSM   = 0x7fffffff7fffffffULL;
    const u64 SGNM   = 0x8000000080000000ULL;

    const float* seqA = g_seq + (size_t)chainA * TT;
    const float* seqB = g_seq + (size_t)chainB * TT;

    u64 h = 0ull, c = 0ull;   // packed (chainA, chainB) state

    for (int t0 = 0; t0 < TT; t0 += 16) {
        const int steps = (TT - t0) < 16 ? (TT - t0) : 16;
        const int tl    = t0 + j;
        u64 xv = 0ull;
        if (tl < TT) {
            const int idx = bwd ? (TT - 1 - tl) : tl;
            xv = pack2(seqA[idx], seqB[idx]);     // two coalesced 64B runs
        }

        for (int i = 0; i < steps; i++) {
            const u64 xt = shfl64_16(xv, i);      // (xA_t, xB_t)
            u64 g0 = fma2(xt, wi[0], bb[0]);
            u64 g1 = fma2(xt, wi[1], bb[1]);
            u64 g2 = fma2(xt, wi[2], bb[2]);
            u64 g3 = fma2(xt, wi[3], bb[3]);
#pragma unroll
            for (int ii = 0; ii < 16; ii++) {
                const u64 hv = shfl64_16(h, ii);  // (hA_ii, hB_ii)
                g0 = fma2(hv, W[0][ii], g0);
                g1 = fma2(hv, W[1][ii], g1);
                g2 = fma2(hv, W[2][ii], g2);
                g3 = fma2(hv, W[3][ii], g3);
            }

            // --- packed sigmoid: 1/(1 + 2^(-x*log2e)) ---
            u64 ig, fg, og;
            {
                u64 t = mul2(g0, NL2E); float a, b; unpack2(t, a, b);
                u64 e = pack2(ex2f(a), ex2f(b));
                u64 d = fma2(e, ONE2, ONE2);
                float d0, d1; unpack2(d, d0, d1);
                ig = pack2(rcpf(d0), rcpf(d1));
            }
            {
                u64 t = mul2(g1, NL2E); float a, b; unpack2(t, a, b);
                u64 e = pack2(ex2f(a), ex2f(b));
                u64 d = fma2(e, ONE2, ONE2);
                float d0, d1; unpack2(d, d0, d1);
                fg = pack2(rcpf(d0), rcpf(d1));
            }
            {
                u64 t = mul2(g3, NL2E); float a, b; unpack2(t, a, b);
                u64 e = pack2(ex2f(a), ex2f(b));
                u64 d = fma2(e, ONE2, ONE2);
                float d0, d1; unpack2(d, d0, d1);
                og = pack2(rcpf(d0), rcpf(d1));
            }

            // --- packed tanh(g2): sign-split (1-e)/(1+e), e = 2^(-2|x|log2e) ---
            u64 gg;
            {
                u64 ax = g2 & ABSM;
                u64 sg = g2 & SGNM;
                u64 t  = mul2(ax, N2L2E); float a, b; unpack2(t, a, b);
                u64 e  = pack2(ex2f(a), ex2f(b));
                u64 n  = fma2(e, NONE2, ONE2);      // 1 - e
                u64 d  = fma2(e, ONE2, ONE2);       // 1 + e
                float d0, d1; unpack2(d, d0, d1);
                u64 r  = mul2(n, pack2(rcpf(d0), rcpf(d1)));
                gg = r | sg;
            }

            c = fma2(fg, c, mul2(ig, gg));

            // --- packed tanh(c) ---
            u64 tc;
            {
                u64 ax = c & ABSM;
                u64 sg = c & SGNM;
                u64 t  = mul2(ax, N2L2E); float a, b; unpack2(t, a, b);
                u64 e  = pack2(ex2f(a), ex2f(b));
                u64 n  = fma2(e, NONE2, ONE2);
                u64 d  = fma2(e, ONE2, ONE2);
                float d0, d1; unpack2(d, d0, d1);
                u64 r  = mul2(n, pack2(rcpf(d0), rcpf(d1)));
                tc = r | sg;
            }

            h = mul2(og, tc);
        }
    }

    float hA, hB; unpack2(h, hA, hB);
    const int off = bwd ? 16 : 0;
    g_feat[chainA * 32 + off + j] = hA;
    g_feat[chainB * 32 + off + j] = hB;
}

// ---------------------------------------------------------------------------
// Kernel 3: out[n,e] = feat[n,:] . lin_w[e,:] + lin_b[e]
// ---------------------------------------------------------------------------
__global__ void __launch_bounds__(256) linear_kernel(
    const float* __restrict__ lw, const float* __restrict__ lb,
    float* __restrict__ out)
{
    const int idx = blockIdx.x * 256 + threadIdx.x;    // 131072 total
    const int n = idx >> 5;
    const int e = idx & 31;
    const float* f = g_feat + n * 32;
    const float* w = lw + e * 32;
    float acc = lb[e];
#pragma unroll
    for (int k = 0; k < 32; k++) acc = fmaf(f[k], w[k], acc);
    out[idx] = acc;
}

// ---------------------------------------------------------------------------
extern "C" void kernel_launch(void* const* d_in, const int* in_sizes, int n_in,
                              void* d_out, int out_size)
{
    const float* x      = (const float*)d_in[0];
    const float* c1w    = (const float*)d_in[1];
    const float* c1b    = (const float*)d_in[2];
    const float* b1g    = (const float*)d_in[3];
    const float* b1b    = (const float*)d_in[4];
    const float* b1m    = (const float*)d_in[5];
    const float* b1v    = (const float*)d_in[6];
    const float* c2w    = (const float*)d_in[7];
    const float* c2b    = (const float*)d_in[8];
    const float* b2g    = (const float*)d_in[9];
    const float* b2b    = (const float*)d_in[10];
    const float* b2m    = (const float*)d_in[11];
    const float* b2v    = (const float*)d_in[12];
    const float* wihf   = (const float*)d_in[13];
    const float* whhf   = (const float*)d_in[14];
    const float* bihf   = (const float*)d_in[15];
    const float* bhhf   = (const float*)d_in[16];
    const float* wihr   = (const float*)d_in[17];
    const float* whhr   = (const float*)d_in[18];
    const float* bihr   = (const float*)d_in[19];
    const float* bhhr   = (const float*)d_in[20];
    const float* lw     = (const float*)d_in[21];
    const float* lb     = (const float*)d_in[22];
    float* out = (float*)d_out;

    prep_kernel<<<NCH, 256>>>(x, c1w, c1b, b1g, b1b, b1m, b1v,
                              c2w, c2b, b2g, b2b, b2m, b2v);
    lstm_kernel<<<512, 128>>>(wihf, whhf, bihf, bhhf,
                              wihr, whhr, bihr, bhhr);
    linear_kernel<<<(NCH * 32) / 256, 256>>>(lw, lb, out);
}